// round 15
// baseline (speedup 1.0000x reference)
#include <cuda_runtime.h>
#include <cuda_bf16.h>
#include <cstdint>
#include <math.h>

#define NP  8192
#define DD  256
#define KNN 10
#define CAP 65        // knn push-buffer entries per row (u64)
#define TOPK 16       // per-(row,half) survivors
#define TOPST 17      // topk row stride in u64 (bank-spread)

// ---------------- scratch (static device globals; no allocation) ------------
__device__ float         g_f[NP * DD];    // f fp32 row-major
__device__ __nv_bfloat16 g_fb[NP * DD];   // f bf16 row-major
__device__ float         g_sq[NP];
__device__ int           g_pi[NP * 32];   // 32 candidates per row (2 halves x 16)
__device__ int           g_idx[NP * KNN];
__device__ float         g_z[NP * DD];
__device__ int           g_bcnti[NP];     // exact integer edge degrees
__device__ int           g_cnt2[NP];      // fill-phase slot counters
__device__ int           g_off[NP];       // CSR offsets (exclusive prefix sum)
__device__ int           g_inv[NP * KNN]; // CSR payload: rows feeding each edge
__device__ float         g_h[NP * DD];

// ---------------- ptx helpers ------------------------------------------------
__device__ __forceinline__ uint32_t smem_u32(const void* p) {
    uint32_t a;
    asm("{ .reg .u64 t; cvta.to.shared.u64 t, %1; cvt.u32.u64 %0, t; }" : "=r"(a) : "l"(p));
    return a;
}
__device__ __forceinline__ void cpasync16(uint32_t dst, const void* src) {
    asm volatile("cp.async.cg.shared.global [%0], [%1], 16;" :: "r"(dst), "l"(src));
}
#define CP_COMMIT() asm volatile("cp.async.commit_group;" ::: "memory")
#define CP_WAIT0()  asm volatile("cp.async.wait_group 0;" ::: "memory")

__device__ __forceinline__ void ldsm_x4(uint32_t* r, uint32_t addr) {
    asm volatile("ldmatrix.sync.aligned.m8n8.x4.shared.b16 {%0,%1,%2,%3}, [%4];"
                 : "=r"(r[0]), "=r"(r[1]), "=r"(r[2]), "=r"(r[3]) : "r"(addr));
}
__device__ __forceinline__ void mma_bf16(float* c, const uint32_t* a,
                                         uint32_t b0, uint32_t b1) {
    asm volatile("mma.sync.aligned.m16n8k16.row.col.f32.bf16.bf16.f32 "
                 "{%0,%1,%2,%3}, {%4,%5,%6,%7}, {%8,%9}, {%0,%1,%2,%3};"
                 : "+f"(c[0]), "+f"(c[1]), "+f"(c[2]), "+f"(c[3])
                 : "r"(a[0]), "r"(a[1]), "r"(a[2]), "r"(a[3]), "r"(b0), "r"(b1));
}
__device__ __forceinline__ uint32_t fkey_map(float k) {
    uint32_t u = __float_as_uint(k);
    return (u & 0x80000000u) ? ~u : (u | 0x80000000u);
}
__device__ __forceinline__ float fkey_unmap(uint32_t m) {
    uint32_t u = (m & 0x80000000u) ? (m & 0x7fffffffu) : ~m;
    return __uint_as_float(u);
}
// f32x2 packed fp32 (sm_100)
__device__ __forceinline__ unsigned long long pack2(float x, float y) {
    unsigned long long r;
    asm("mov.b64 %0, {%1, %2};" : "=l"(r) : "f"(x), "f"(y));
    return r;
}
__device__ __forceinline__ float2 unpack2(unsigned long long v) {
    float2 r;
    asm("mov.b64 {%0, %1}, %2;" : "=f"(r.x), "=f"(r.y) : "l"(v));
    return r;
}
#define FMA2(d, a, b) asm("fma.rn.f32x2 %0, %1, %2, %0;" : "+l"(d) : "l"(a), "l"(b))

// ---------------- GEMM 1: g_f = x @ Wd (fp32) + g_fb (bf16) + g_sq ----------
__global__ __launch_bounds__(256) void gemm_f_kernel(const float* __restrict__ A,
                                                     const float* __restrict__ B) {
    __shared__ float As[16][64];
    __shared__ float Bs[16][64];
    int t  = threadIdx.x;
    int tx = t % 16, ty = t / 16;
    int rb = blockIdx.y * 64, cb = blockIdx.x * 64;
    unsigned long long accp[4][2] = {};
    for (int k0 = 0; k0 < DD; k0 += 16) {
        {
            int row = t >> 2, kq = (t & 3) * 4;
            float4 v = *(const float4*)&A[(rb + row) * DD + k0 + kq];
            As[kq + 0][row] = v.x; As[kq + 1][row] = v.y;
            As[kq + 2][row] = v.z; As[kq + 3][row] = v.w;
        }
        {
            int krow = t >> 4, cq = (t & 15) * 4;
            *(float4*)&Bs[krow][cq] = *(const float4*)&B[(k0 + krow) * DD + cb + cq];
        }
        __syncthreads();
        #pragma unroll
        for (int kk = 0; kk < 16; kk++) {
            float4 av = *(const float4*)&As[kk][ty * 4];
            float4 bv = *(const float4*)&Bs[kk][tx * 4];
            unsigned long long bb0 = pack2(bv.x, bv.y);
            unsigned long long bb1 = pack2(bv.z, bv.w);
            float a[4] = {av.x, av.y, av.z, av.w};
            #pragma unroll
            for (int i = 0; i < 4; i++) {
                unsigned long long aa = pack2(a[i], a[i]);
                FMA2(accp[i][0], aa, bb0);
                FMA2(accp[i][1], aa, bb1);
            }
        }
        __syncthreads();
    }
    int lane = t & 31;
    #pragma unroll
    for (int i = 0; i < 4; i++) {
        int r = rb + ty * 4 + i;
        int c = cb + tx * 4;
        float2 u0 = unpack2(accp[i][0]);
        float2 u1 = unpack2(accp[i][1]);
        float4 vv = make_float4(u0.x, u0.y, u1.x, u1.y);
        *(float4*)&g_f[r * DD + c] = vv;
        __nv_bfloat162 b01 = __floats2bfloat162_rn(vv.x, vv.y);
        __nv_bfloat162 b23 = __floats2bfloat162_rn(vv.z, vv.w);
        uint2 pk;
        pk.x = *(uint32_t*)&b01;
        pk.y = *(uint32_t*)&b23;
        *(uint2*)&g_fb[r * DD + c] = pk;
        // fused sq-norm partial: reduce over the 16-thread tx group
        float sqp = vv.x * vv.x + vv.y * vv.y + vv.z * vv.z + vv.w * vv.w;
        #pragma unroll
        for (int o = 8; o > 0; o >>= 1)
            sqp += __shfl_xor_sync(0xffffffffu, sqp, o);
        if ((lane & 15) == 0) atomicAdd(&g_sq[r], sqp);
    }
}

// ---------------- GEMM 2: out = h @ W + bias --------------------------------
__global__ __launch_bounds__(256) void gemm_out_kernel(const float* __restrict__ B,
                                                       const float* __restrict__ bias,
                                                       float* __restrict__ C) {
    __shared__ float As[16][64];
    __shared__ float Bs[16][64];
    int t  = threadIdx.x;
    int tx = t % 16, ty = t / 16;
    int rb = blockIdx.y * 64, cb = blockIdx.x * 64;
    const float* A = g_h;
    unsigned long long accp[4][2] = {};
    for (int k0 = 0; k0 < DD; k0 += 16) {
        {
            int row = t >> 2, kq = (t & 3) * 4;
            float4 v = *(const float4*)&A[(rb + row) * DD + k0 + kq];
            As[kq + 0][row] = v.x; As[kq + 1][row] = v.y;
            As[kq + 2][row] = v.z; As[kq + 3][row] = v.w;
        }
        {
            int krow = t >> 4, cq = (t & 15) * 4;
            *(float4*)&Bs[krow][cq] = *(const float4*)&B[(k0 + krow) * DD + cb + cq];
        }
        __syncthreads();
        #pragma unroll
        for (int kk = 0; kk < 16; kk++) {
            float4 av = *(const float4*)&As[kk][ty * 4];
            float4 bv = *(const float4*)&Bs[kk][tx * 4];
            unsigned long long bb0 = pack2(bv.x, bv.y);
            unsigned long long bb1 = pack2(bv.z, bv.w);
            float a[4] = {av.x, av.y, av.z, av.w};
            #pragma unroll
            for (int i = 0; i < 4; i++) {
                unsigned long long aa = pack2(a[i], a[i]);
                FMA2(accp[i][0], aa, bb0);
                FMA2(accp[i][1], aa, bb1);
            }
        }
        __syncthreads();
    }
    #pragma unroll
    for (int i = 0; i < 4; i++) {
        int r = rb + ty * 4 + i;
        int c = cb + tx * 4;
        float2 u0 = unpack2(accp[i][0]);
        float2 u1 = unpack2(accp[i][1]);
        C[r * DD + c + 0] = u0.x + bias[c + 0];
        C[r * DD + c + 1] = u0.y + bias[c + 1];
        C[r * DD + c + 2] = u1.x + bias[c + 2];
        C[r * DD + c + 3] = u1.y + bias[c + 3];
    }
}

// ---------------- coarse knn: mma.sync bf16 + threshold filter --------------
// (unchanged from R13; sync order CP_WAIT0 -> __syncthreads -> prefetch is
// load-bearing for cp.async cross-thread visibility)
__global__ __launch_bounds__(256, 2) void knn_coarse_kernel() {
    extern __shared__ char dsm[];
    // layout: A 32768 | B0 16384 | B1 16384 | buf 33280 | topk 8704 |
    //         sqs 512 | cnt 256 | wvv 256   (total 108544)
    unsigned long long* buf  = (unsigned long long*)(dsm + 65536);
    unsigned long long* topk = (unsigned long long*)(dsm + 98816);
    float* sqs = (float*)(dsm + 107520);
    int*   cnt = (int*)(dsm + 108032);
    float* wvv = (float*)(dsm + 108288);

    int t = threadIdx.x, lane = t & 31, warp = t >> 5;
    int wm = warp & 1, wn = warp >> 1;
    int rb = blockIdx.y * 64;
    int half = blockIdx.x;
    int cbase = half * (NP / 2);

    uint32_t Abase  = smem_u32(dsm);
    uint32_t Bbase0 = Abase + 32768;
    uint32_t Bbase1 = Abase + 49152;

    const float INF = __int_as_float(0x7f800000);

    // init per-row structures
    if (t < 64) {
        #pragma unroll
        for (int k = 0; k < TOPK; k++) topk[t * TOPST + k] = ~0ULL;
        cnt[t] = 0;
        wvv[t] = INF;
    }

    // precomputed per-thread B-chunk load offsets (smem, gmem bytes)
    uint32_t sOffB[4]; uint32_t gOffB[4];
    #pragma unroll
    for (int i = 0; i < 4; i++) {
        int idx = t + 256 * i;
        int id = idx >> 3, g = idx & 7;
        sOffB[i] = (uint32_t)(id * 128 + ((g ^ (id & 7)) << 4));
        gOffB[i] = (uint32_t)(id * DD * 2 + g * 16);
    }
    const char* gB = (const char*)&g_fb[(size_t)cbase * DD];

    // A tile (64 rows x 256 k), granule-swizzled: g' = g ^ (row&7)
    #pragma unroll
    for (int i = 0; i < 8; i++) {
        int idx = t + 256 * i;
        int id = idx >> 5, g = idx & 31;
        cpasync16(Abase + id * 512 + ((g ^ (id & 7)) << 4),
                  &g_fb[(rb + id) * DD + g * 8]);
    }
    // B chunk 0
    #pragma unroll
    for (int i = 0; i < 4; i++)
        cpasync16(Bbase0 + sOffB[i], gB + gOffB[i]);
    CP_COMMIT();

    // per-thread ldmatrix addressing (same fragment mapping as R5/R6)
    int arow = wm * 32 + (lane & 7) + ((lane & 8) ? 8 : 0);
    uint32_t Arow0 = Abase + arow * 512;
    uint32_t Arow1 = Arow0 + 16 * 512;
    int sw  = lane & 7;
    int aka = (lane & 16) ? 1 : 0;                   // A: k +8 selector
    int bro = (lane & 7) + ((lane & 16) ? 8 : 0);    // B: n-row within pair
    int bka = (lane & 8) ? 1 : 0;                    // B: k +8 selector
    uint32_t Brow0 = (uint32_t)((wn * 32 + bro) * 128);       // pi=0 row base
    uint32_t Brow1 = (uint32_t)((wn * 32 + 16 + bro) * 128);  // pi=1 row base

    int rq = lane >> 2, cq2 = (lane & 3) * 2;
    float wvreg[4] = {INF, INF, INF, INF};           // [mi*2+qh]

    float acc[2][4][4];

    const char* pNext = gB + 128;                    // source base of chunk 1

    #pragma unroll 1
    for (int jt = 0; jt < 32; jt++) {
        #pragma unroll
        for (int kc = 0; kc < 4; kc++) {
            CP_WAIT0();
            __syncthreads();

            if (kc == 0 && t < 128) sqs[t] = g_sq[cbase + jt * 128 + t];

            // prefetch next chunk (compile-time buffer parity)
            if (jt < 31 || kc < 3) {
                uint32_t bb = ((kc + 1) & 1) ? Bbase1 : Bbase0;
                #pragma unroll
                for (int i = 0; i < 4; i++)
                    cpasync16(bb + sOffB[i], pNext + gOffB[i]);
                CP_COMMIT();
                pNext += (kc == 2) ? (128 * DD * 2 - 3 * 128) : 128;
            }

            if (kc == 0) {
                #pragma unroll
                for (int mi = 0; mi < 2; mi++)
                    #pragma unroll
                    for (int ni = 0; ni < 4; ni++)
                        #pragma unroll
                        for (int q = 0; q < 4; q++) acc[mi][ni][q] = 0.f;
            }

            uint32_t Bb = (kc & 1) ? Bbase1 : Bbase0;
            #pragma unroll
            for (int s = 0; s < 4; s++) {            // 4 k16 steps / 64-k chunk
                int ga = kc * 8 + s * 2 + aka;       // compile-time kc, s
                uint32_t a0[4], a1[4];
                ldsm_x4(a0, Arow0 + ((ga ^ sw) << 4));
                ldsm_x4(a1, Arow1 + ((ga ^ sw) << 4));
                int gb = s * 2 + bka;
                uint32_t b0[4], b1[4];
                ldsm_x4(b0, Bb + Brow0 + ((gb ^ sw) << 4));
                ldsm_x4(b1, Bb + Brow1 + ((gb ^ sw) << 4));
                mma_bf16(acc[0][0], a0, b0[0], b0[1]);
                mma_bf16(acc[0][1], a0, b0[2], b0[3]);
                mma_bf16(acc[1][0], a1, b0[0], b0[1]);
                mma_bf16(acc[1][1], a1, b0[2], b0[3]);
                mma_bf16(acc[0][2], a0, b1[0], b1[1]);
                mma_bf16(acc[0][3], a0, b1[2], b1[3]);
                mma_bf16(acc[1][2], a1, b1[0], b1[1]);
                mma_bf16(acc[1][3], a1, b1[2], b1[3]);
            }

            if (kc == 3) {
                int jb = cbase + jt * 128;
                if (jt == 0) {
                    // bootstrap: per-thread top-4 of its 8 cols per owned row
                    #pragma unroll
                    for (int mi = 0; mi < 2; mi++)
                        #pragma unroll
                        for (int qh = 0; qh < 2; qh++) {
                            int rl = wm * 32 + mi * 16 + qh * 8 + rq;
                            float bv[4] = {INF, INF, INF, INF};
                            int bc[4] = {0, 0, 0, 0};
                            #pragma unroll
                            for (int ni = 0; ni < 4; ni++)
                                #pragma unroll
                                for (int ql = 0; ql < 2; ql++) {
                                    int cl = wn * 32 + ni * 8 + cq2 + ql;
                                    float k = fmaf(-2.f, acc[mi][ni][qh * 2 + ql], sqs[cl]);
                                    if (k < bv[3]) {
                                        if (k < bv[2]) {
                                            bv[3] = bv[2]; bc[3] = bc[2];
                                            if (k < bv[1]) {
                                                bv[2] = bv[1]; bc[2] = bc[1];
                                                if (k < bv[0]) {
                                                    bv[1] = bv[0]; bc[1] = bc[0];
                                                    bv[0] = k; bc[0] = cl;
                                                } else { bv[1] = k; bc[1] = cl; }
                                            } else { bv[2] = k; bc[2] = cl; }
                                        } else { bv[3] = k; bc[3] = cl; }
                                    }
                                }
                            #pragma unroll
                            for (int s2 = 0; s2 < 4; s2++) {
                                int pos = atomicAdd(&cnt[rl], 1);
                                if (pos < CAP)
                                    buf[rl * CAP + pos] =
                                        ((unsigned long long)fkey_map(bv[s2]) << 32) |
                                        (unsigned)(jb + bc[s2]);
                            }
                        }
                } else {
                    // threshold filter: push survivors only
                    #pragma unroll
                    for (int mi = 0; mi < 2; mi++)
                        #pragma unroll
                        for (int qh = 0; qh < 2; qh++) {
                            float wv = wvreg[mi * 2 + qh];
                            int rl = wm * 32 + mi * 16 + qh * 8 + rq;
                            #pragma unroll
                            for (int ni = 0; ni < 4; ni++)
                                #pragma unroll
                                for (int ql = 0; ql < 2; ql++) {
                                    int cl = wn * 32 + ni * 8 + cq2 + ql;
                                    float k = fmaf(-2.f, acc[mi][ni][qh * 2 + ql], sqs[cl]);
                                    if (k < wv) {
                                        int pos = atomicAdd(&cnt[rl], 1);
                                        if (pos < CAP)
                                            buf[rl * CAP + pos] =
                                                ((unsigned long long)fkey_map(k) << 32) |
                                                (unsigned)(jb + cl);
                                    }
                                }
                        }
                }

                if ((jt & (jt + 1)) == 0) {   // window boundary: jt = 2^m - 1
                    __syncthreads();
                    if (t < 64) {
                        int n = cnt[t]; if (n > CAP) n = CAP;
                        unsigned long long* tk = &topk[t * TOPST];
                        for (int e = 0; e < n; e++) {
                            unsigned long long v = buf[t * CAP + e];
                            int pm = 0; unsigned long long mv = tk[0];
                            #pragma unroll
                            for (int k = 1; k < TOPK; k++)
                                if (tk[k] > mv) { mv = tk[k]; pm = k; }
                            if (v < mv) tk[pm] = v;
                        }
                        cnt[t] = 0;
                        unsigned long long mv = tk[0];
                        #pragma unroll
                        for (int k = 1; k < TOPK; k++)
                            if (tk[k] > mv) mv = tk[k];
                        wvv[t] = fkey_unmap((uint32_t)(mv >> 32));
                    }
                    __syncthreads();
                    #pragma unroll
                    for (int mi = 0; mi < 2; mi++)
                        #pragma unroll
                        for (int qh = 0; qh < 2; qh++)
                            wvreg[mi * 2 + qh] = wvv[wm * 32 + mi * 16 + qh * 8 + rq];
                }
            }
        }
    }

    // emit 16 candidates per (row, half); jt=31 consolidation already ran
    if (t < 64) {
        int row = rb + t;
        #pragma unroll
        for (int s = 0; s < TOPK; s++)
            g_pi[row * 32 + half * 16 + s] =
                (int)(topk[t * TOPST + s] & 0xffffffffULL);
    }
}

// ---------------- exact refine: warp-cooperative, coalesced -----------------
__global__ __launch_bounds__(256) void refine_kernel() {
    int t = threadIdx.x, w = t >> 5, l = t & 31;
    int i = blockIdx.x * 8 + w;
    const float4* fi4 = (const float4*)&g_f[i * DD];
    float4 a0 = fi4[l], a1 = fi4[l + 32];
    int jl = g_pi[i * 32 + l];
    float sql = g_sq[jl];
    unsigned long long pk = ~0ULL;
    #pragma unroll 8
    for (int c = 0; c < 32; c++) {
        int j = __shfl_sync(0xffffffffu, jl, c);
        float sq = __shfl_sync(0xffffffffu, sql, c);
        const float4* fj4 = (const float4*)&g_f[j * DD];
        float4 b0 = fj4[l], b1 = fj4[l + 32];
        float p = a0.x * b0.x;
        p = fmaf(a0.y, b0.y, p);
        p = fmaf(a0.z, b0.z, p);
        p = fmaf(a0.w, b0.w, p);
        p = fmaf(a1.x, b1.x, p);
        p = fmaf(a1.y, b1.y, p);
        p = fmaf(a1.z, b1.z, p);
        p = fmaf(a1.w, b1.w, p);
        #pragma unroll
        for (int o = 16; o > 0; o >>= 1)
            p += __shfl_xor_sync(0xffffffffu, p, o);
        float key = sq - 2.f * p;
        unsigned long long v =
            ((unsigned long long)fkey_map(key) << 32) | (unsigned)j;
        if (l == c) pk = v;
    }
    #pragma unroll
    for (int r = 0; r < KNN; r++) {
        unsigned long long m = pk;
        #pragma unroll
        for (int o = 16; o > 0; o >>= 1) {
            unsigned long long other = __shfl_xor_sync(0xffffffffu, m, o);
            if (other < m) m = other;
        }
        if (l == 0) g_idx[i * KNN + r] = (int)(m & 0xffffffffULL);
        if (pk == m) pk = 0xFFFFFFFFFFFFFFFFULL;
    }
}

// ---------------- Laplacian apply: exact (uncapped) CSR ---------------------
__global__ __launch_bounds__(256) void zero_kernel() {
    int tid = blockIdx.x * blockDim.x + threadIdx.x;
    if (tid < NP) { g_bcnti[tid] = 0; g_cnt2[tid] = 0; g_sq[tid] = 0.f; }
}

// pass 1: exact degrees
__global__ __launch_bounds__(256) void count_kernel() {
    int ent = blockIdx.x * 256 + threadIdx.x;   // 0 .. NP*KNN-1
    atomicAdd(&g_bcnti[g_idx[ent]], 1);
}

// pass 2: exclusive prefix sum of 8192 degrees (single block, 256 threads)
__global__ __launch_bounds__(256) void offset_kernel() {
    __shared__ int warpsum[8];
    __shared__ int wexc[8];
    int t = threadIdx.x, lane = t & 31, wid = t >> 5;
    int base = t * 32;
    int local[32];
    int s = 0;
    #pragma unroll
    for (int q = 0; q < 32; q++) { local[q] = s; s += g_bcnti[base + q]; }
    // inclusive warp scan of per-thread totals
    int v = s;
    #pragma unroll
    for (int o = 1; o < 32; o <<= 1) {
        int u = __shfl_up_sync(0xffffffffu, v, o);
        if (lane >= o) v += u;
    }
    if (lane == 31) warpsum[wid] = v;
    __syncthreads();
    if (t == 0) {
        int run = 0;
        #pragma unroll
        for (int k = 0; k < 8; k++) { wexc[k] = run; run += warpsum[k]; }
    }
    __syncthreads();
    int texc = wexc[wid] + (v - s);             // exclusive base for this thread
    #pragma unroll
    for (int q = 0; q < 32; q++) g_off[base + q] = texc + local[q];
}

// pass 3: fill CSR payload
__global__ __launch_bounds__(256) void fill_kernel() {
    int ent = blockIdx.x * 256 + threadIdx.x;   // 0 .. NP*KNN-1
    int e = g_idx[ent];
    int i = ent / KNN;
    int slot = atomicAdd(&g_cnt2[e], 1);
    g_inv[g_off[e] + slot] = i;
}

// z[e] = cnorm * sum_{i in inv[e]} x[i]   (fully written; no pre-zero needed)
__global__ __launch_bounds__(256) void zgather_kernel(const float* __restrict__ x) {
    int t = threadIdx.x;
    int e = blockIdx.x * 4 + (t >> 6);
    int cq = (t & 63) << 2;
    int deg  = g_bcnti[e];
    int base = g_off[e];
    float4 acc = make_float4(0.f, 0.f, 0.f, 0.f);
    const int* inv = &g_inv[base];
    for (int d = 0; d < deg; d++) {
        int i = inv[d];
        float4 xv = *(const float4*)&x[i * DD + cq];
        acc.x += xv.x; acc.y += xv.y; acc.z += xv.z; acc.w += xv.w;
    }
    const float cnorm = 0.31622776601683794f;  // 1/sqrt(10+1e-10)
    float4 zv = make_float4(cnorm * acc.x, cnorm * acc.y,
                            cnorm * acc.z, cnorm * acc.w);
    *(float4*)&g_z[e * DD + cq] = zv;
}

__global__ __launch_bounds__(256) void gather_kernel(const float* __restrict__ x) {
    __shared__ int   sidx[4][KNN];
    __shared__ float sbis[4][KNN];
    int t = threadIdx.x;
    int i0 = blockIdx.x * 4;
    if (t < 4 * KNN) {
        int r = t / KNN, k = t % KNN;
        int e = g_idx[(i0 + r) * KNN + k];
        sidx[r][k] = e;
        sbis[r][k] = 1.0f / sqrtf((float)g_bcnti[e] + 1e-10f);
    }
    __syncthreads();
    int s = t >> 6;
    int cq = (t & 63) << 2;
    float4 acc = make_float4(0.f, 0.f, 0.f, 0.f);
    #pragma unroll
    for (int k = 0; k < KNN; k++) {
        int e = sidx[s][k];
        float b = sbis[s][k];
        float4 zv = *(const float4*)&g_z[e * DD + cq];
        acc.x = fmaf(b, zv.x, acc.x);
        acc.y = fmaf(b, zv.y, acc.y);
        acc.z = fmaf(b, zv.z, acc.z);
        acc.w = fmaf(b, zv.w, acc.w);
    }
    const float hc = 0.5f * 0.31622776601683794f;
    float4 xv = *(const float4*)&x[(i0 + s) * DD + cq];
    float4 h;
    h.x = xv.x - hc * acc.x;
    h.y = xv.y - hc * acc.y;
    h.z = xv.z - hc * acc.z;
    h.w = xv.w - hc * acc.w;
    *(float4*)&g_h[(i0 + s) * DD + cq] = h;
}

// ---------------- launch -----------------------------------------------------
extern "C" void kernel_launch(void* const* d_in, const int* in_sizes, int n_in,
                              void* d_out, int out_size) {
    const float* x    = (const float*)d_in[0];   // (8192, 256)
    const float* w    = (const float*)d_in[1];   // (256, 256)
    const float* wd   = (const float*)d_in[2];   // (256, 256)
    const float* bias = (const float*)d_in[3];   // (256,)
    float* out = (float*)d_out;                  // (8192, 256)

    const int KNN_SMEM = 108544;
    cudaFuncSetAttribute(knn_coarse_kernel,
                         cudaFuncAttributeMaxDynamicSharedMemorySize, KNN_SMEM);

    zero_kernel<<<NP / 256, 256>>>();                    // counters + g_sq = 0
    gemm_f_kernel<<<dim3(DD / 64, NP / 64), 256>>>(x, wd);  // f, fb, sq (fused)
    knn_coarse_kernel<<<dim3(2, NP / 64), 256, KNN_SMEM>>>();
    refine_kernel<<<NP / 8, 256>>>();
    count_kernel<<<NP * KNN / 256, 256>>>();             // exact degrees
    offset_kernel<<<1, 256>>>();                         // CSR offsets
    fill_kernel<<<NP * KNN / 256, 256>>>();              // CSR payload
    zgather_kernel<<<NP / 4, 256>>>(x);                  // z = c * H^T x
    gather_kernel<<<NP / 4, 256>>>(x);                   // h = x - 0.5c H B^-1/2 z
    gemm_out_kernel<<<dim3(DD / 64, NP / 64), 256>>>(w, bias, out);
}

// round 16
// speedup vs baseline: 1.1210x; 1.1210x over previous
#include <cuda_runtime.h>
#include <cuda_bf16.h>
#include <cstdint>
#include <math.h>

#define NP  8192
#define DD  256
#define KNN 10
#define CAP 65        // push-buffer entries per row (u64)
#define TOPK 16       // per-(row,half) survivors
#define TOPST 17      // topk row stride in u64 (bank-spread)

// ---------------- scratch (static device globals; no allocation) ------------
__device__ float         g_f[NP * DD];    // f fp32 row-major
__device__ __nv_bfloat16 g_fb[NP * DD];   // f bf16 row-major
__device__ float         g_sq[NP];
__device__ int           g_pi[NP * 32];   // 32 candidates per row (2 halves x 16)
__device__ int           g_idx[NP * KNN];
__device__ float         g_z[NP * DD];
__device__ float         g_bcnt[NP];
__device__ float         g_h[NP * DD];

// ---------------- ptx helpers ------------------------------------------------
__device__ __forceinline__ uint32_t smem_u32(const void* p) {
    uint32_t a;
    asm("{ .reg .u64 t; cvta.to.shared.u64 t, %1; cvt.u32.u64 %0, t; }" : "=r"(a) : "l"(p));
    return a;
}
__device__ __forceinline__ void cpasync16(uint32_t dst, const void* src) {
    asm volatile("cp.async.cg.shared.global [%0], [%1], 16;" :: "r"(dst), "l"(src));
}
#define CP_COMMIT() asm volatile("cp.async.commit_group;" ::: "memory")
#define CP_WAIT0()  asm volatile("cp.async.wait_group 0;" ::: "memory")

__device__ __forceinline__ void ldsm_x4(uint32_t* r, uint32_t addr) {
    asm volatile("ldmatrix.sync.aligned.m8n8.x4.shared.b16 {%0,%1,%2,%3}, [%4];"
                 : "=r"(r[0]), "=r"(r[1]), "=r"(r[2]), "=r"(r[3]) : "r"(addr));
}
__device__ __forceinline__ void mma_bf16(float* c, const uint32_t* a,
                                         uint32_t b0, uint32_t b1) {
    asm volatile("mma.sync.aligned.m16n8k16.row.col.f32.bf16.bf16.f32 "
                 "{%0,%1,%2,%3}, {%4,%5,%6,%7}, {%8,%9}, {%0,%1,%2,%3};"
                 : "+f"(c[0]), "+f"(c[1]), "+f"(c[2]), "+f"(c[3])
                 : "r"(a[0]), "r"(a[1]), "r"(a[2]), "r"(a[3]), "r"(b0), "r"(b1));
}
__device__ __forceinline__ uint32_t fkey_map(float k) {
    uint32_t u = __float_as_uint(k);
    return (u & 0x80000000u) ? ~u : (u | 0x80000000u);
}
__device__ __forceinline__ float fkey_unmap(uint32_t m) {
    uint32_t u = (m & 0x80000000u) ? (m & 0x7fffffffu) : ~m;
    return __uint_as_float(u);
}
// f32x2 packed fp32 (sm_100)
__device__ __forceinline__ unsigned long long pack2(float x, float y) {
    unsigned long long r;
    asm("mov.b64 %0, {%1, %2};" : "=l"(r) : "f"(x), "f"(y));
    return r;
}
__device__ __forceinline__ float2 unpack2(unsigned long long v) {
    float2 r;
    asm("mov.b64 {%0, %1}, %2;" : "=f"(r.x), "=f"(r.y) : "l"(v));
    return r;
}
#define FMA2(d, a, b) asm("fma.rn.f32x2 %0, %1, %2, %0;" : "+l"(d) : "l"(a), "l"(b))

// ---------------- GEMM 1: g_f = x @ Wd (fp32) + g_fb (bf16) + g_sq ----------
__global__ __launch_bounds__(256) void gemm_f_kernel(const float* __restrict__ A,
                                                     const float* __restrict__ B) {
    __shared__ float As[16][64];
    __shared__ float Bs[16][64];
    int t  = threadIdx.x;
    int tx = t % 16, ty = t / 16;
    int rb = blockIdx.y * 64, cb = blockIdx.x * 64;
    unsigned long long accp[4][2] = {};
    for (int k0 = 0; k0 < DD; k0 += 16) {
        {
            int row = t >> 2, kq = (t & 3) * 4;
            float4 v = *(const float4*)&A[(rb + row) * DD + k0 + kq];
            As[kq + 0][row] = v.x; As[kq + 1][row] = v.y;
            As[kq + 2][row] = v.z; As[kq + 3][row] = v.w;
        }
        {
            int krow = t >> 4, cq = (t & 15) * 4;
            *(float4*)&Bs[krow][cq] = *(const float4*)&B[(k0 + krow) * DD + cb + cq];
        }
        __syncthreads();
        #pragma unroll
        for (int kk = 0; kk < 16; kk++) {
            float4 av = *(const float4*)&As[kk][ty * 4];
            float4 bv = *(const float4*)&Bs[kk][tx * 4];
            unsigned long long bb0 = pack2(bv.x, bv.y);
            unsigned long long bb1 = pack2(bv.z, bv.w);
            float a[4] = {av.x, av.y, av.z, av.w};
            #pragma unroll
            for (int i = 0; i < 4; i++) {
                unsigned long long aa = pack2(a[i], a[i]);
                FMA2(accp[i][0], aa, bb0);
                FMA2(accp[i][1], aa, bb1);
            }
        }
        __syncthreads();
    }
    int lane = t & 31;
    #pragma unroll
    for (int i = 0; i < 4; i++) {
        int r = rb + ty * 4 + i;
        int c = cb + tx * 4;
        float2 u0 = unpack2(accp[i][0]);
        float2 u1 = unpack2(accp[i][1]);
        float4 vv = make_float4(u0.x, u0.y, u1.x, u1.y);
        *(float4*)&g_f[r * DD + c] = vv;
        __nv_bfloat162 b01 = __floats2bfloat162_rn(vv.x, vv.y);
        __nv_bfloat162 b23 = __floats2bfloat162_rn(vv.z, vv.w);
        uint2 pk;
        pk.x = *(uint32_t*)&b01;
        pk.y = *(uint32_t*)&b23;
        *(uint2*)&g_fb[r * DD + c] = pk;
        // fused sq-norm partial: reduce over the 16-thread tx group
        float sqp = vv.x * vv.x + vv.y * vv.y + vv.z * vv.z + vv.w * vv.w;
        #pragma unroll
        for (int o = 8; o > 0; o >>= 1)
            sqp += __shfl_xor_sync(0xffffffffu, sqp, o);
        if ((lane & 15) == 0) atomicAdd(&g_sq[r], sqp);
    }
}

// ---------------- GEMM 2: out = h @ W + bias --------------------------------
__global__ __launch_bounds__(256) void gemm_out_kernel(const float* __restrict__ B,
                                                       const float* __restrict__ bias,
                                                       float* __restrict__ C) {
    __shared__ float As[16][64];
    __shared__ float Bs[16][64];
    int t  = threadIdx.x;
    int tx = t % 16, ty = t / 16;
    int rb = blockIdx.y * 64, cb = blockIdx.x * 64;
    const float* A = g_h;
    unsigned long long accp[4][2] = {};
    for (int k0 = 0; k0 < DD; k0 += 16) {
        {
            int row = t >> 2, kq = (t & 3) * 4;
            float4 v = *(const float4*)&A[(rb + row) * DD + k0 + kq];
            As[kq + 0][row] = v.x; As[kq + 1][row] = v.y;
            As[kq + 2][row] = v.z; As[kq + 3][row] = v.w;
        }
        {
            int krow = t >> 4, cq = (t & 15) * 4;
            *(float4*)&Bs[krow][cq] = *(const float4*)&B[(k0 + krow) * DD + cb + cq];
        }
        __syncthreads();
        #pragma unroll
        for (int kk = 0; kk < 16; kk++) {
            float4 av = *(const float4*)&As[kk][ty * 4];
            float4 bv = *(const float4*)&Bs[kk][tx * 4];
            unsigned long long bb0 = pack2(bv.x, bv.y);
            unsigned long long bb1 = pack2(bv.z, bv.w);
            float a[4] = {av.x, av.y, av.z, av.w};
            #pragma unroll
            for (int i = 0; i < 4; i++) {
                unsigned long long aa = pack2(a[i], a[i]);
                FMA2(accp[i][0], aa, bb0);
                FMA2(accp[i][1], aa, bb1);
            }
        }
        __syncthreads();
    }
    #pragma unroll
    for (int i = 0; i < 4; i++) {
        int r = rb + ty * 4 + i;
        int c = cb + tx * 4;
        float2 u0 = unpack2(accp[i][0]);
        float2 u1 = unpack2(accp[i][1]);
        C[r * DD + c + 0] = u0.x + bias[c + 0];
        C[r * DD + c + 1] = u0.y + bias[c + 1];
        C[r * DD + c + 2] = u1.x + bias[c + 2];
        C[r * DD + c + 3] = u1.y + bias[c + 3];
    }
}

// ---------------- coarse knn: mma.sync bf16 + threshold filter --------------
// CTA: 64 rows x one 4096-col half, 2 CTAs/SM. kc fully unrolled (compile-time
// buffer parity / addressing); cp.async offsets precomputed per thread.
// Sync order (load-bearing): CP_WAIT0 -> __syncthreads -> prefetch. The wait
// MUST precede the barrier so every thread's cp.async data is visible to all.
__global__ __launch_bounds__(256, 2) void knn_coarse_kernel() {
    extern __shared__ char dsm[];
    // layout: A 32768 | B0 16384 | B1 16384 | buf 33280 | topk 8704 |
    //         sqs 512 | cnt 256 | wvv 256   (total 108544)
    unsigned long long* buf  = (unsigned long long*)(dsm + 65536);
    unsigned long long* topk = (unsigned long long*)(dsm + 98816);
    float* sqs = (float*)(dsm + 107520);
    int*   cnt = (int*)(dsm + 108032);
    float* wvv = (float*)(dsm + 108288);

    int t = threadIdx.x, lane = t & 31, warp = t >> 5;
    int wm = warp & 1, wn = warp >> 1;
    int rb = blockIdx.y * 64;
    int half = blockIdx.x;
    int cbase = half * (NP / 2);

    uint32_t Abase  = smem_u32(dsm);
    uint32_t Bbase0 = Abase + 32768;
    uint32_t Bbase1 = Abase + 49152;

    const float INF = __int_as_float(0x7f800000);

    // init per-row structures
    if (t < 64) {
        #pragma unroll
        for (int k = 0; k < TOPK; k++) topk[t * TOPST + k] = ~0ULL;
        cnt[t] = 0;
        wvv[t] = INF;
    }

    // precomputed per-thread B-chunk load offsets (smem, gmem bytes)
    uint32_t sOffB[4]; uint32_t gOffB[4];
    #pragma unroll
    for (int i = 0; i < 4; i++) {
        int idx = t + 256 * i;
        int id = idx >> 3, g = idx & 7;
        sOffB[i] = (uint32_t)(id * 128 + ((g ^ (id & 7)) << 4));
        gOffB[i] = (uint32_t)(id * DD * 2 + g * 16);
    }
    const char* gB = (const char*)&g_fb[(size_t)cbase * DD];

    // A tile (64 rows x 256 k), granule-swizzled: g' = g ^ (row&7)
    #pragma unroll
    for (int i = 0; i < 8; i++) {
        int idx = t + 256 * i;
        int id = idx >> 5, g = idx & 31;
        cpasync16(Abase + id * 512 + ((g ^ (id & 7)) << 4),
                  &g_fb[(rb + id) * DD + g * 8]);
    }
    // B chunk 0
    #pragma unroll
    for (int i = 0; i < 4; i++)
        cpasync16(Bbase0 + sOffB[i], gB + gOffB[i]);
    CP_COMMIT();

    // per-thread ldmatrix addressing (same fragment mapping as R5/R6)
    int arow = wm * 32 + (lane & 7) + ((lane & 8) ? 8 : 0);
    uint32_t Arow0 = Abase + arow * 512;
    uint32_t Arow1 = Arow0 + 16 * 512;
    int sw  = lane & 7;
    int aka = (lane & 16) ? 1 : 0;                   // A: k +8 selector
    int bro = (lane & 7) + ((lane & 16) ? 8 : 0);    // B: n-row within pair
    int bka = (lane & 8) ? 1 : 0;                    // B: k +8 selector
    uint32_t Brow0 = (uint32_t)((wn * 32 + bro) * 128);       // pi=0 row base
    uint32_t Brow1 = (uint32_t)((wn * 32 + 16 + bro) * 128);  // pi=1 row base

    int rq = lane >> 2, cq2 = (lane & 3) * 2;
    float wvreg[4] = {INF, INF, INF, INF};           // [mi*2+qh]

    float acc[2][4][4];

    const char* pNext = gB + 128;                    // source base of chunk 1

    #pragma unroll 1
    for (int jt = 0; jt < 32; jt++) {
        #pragma unroll
        for (int kc = 0; kc < 4; kc++) {
            CP_WAIT0();
            __syncthreads();

            if (kc == 0 && t < 128) sqs[t] = g_sq[cbase + jt * 128 + t];

            // prefetch next chunk (compile-time buffer parity)
            if (jt < 31 || kc < 3) {
                uint32_t bb = ((kc + 1) & 1) ? Bbase1 : Bbase0;
                #pragma unroll
                for (int i = 0; i < 4; i++)
                    cpasync16(bb + sOffB[i], pNext + gOffB[i]);
                CP_COMMIT();
                pNext += (kc == 2) ? (128 * DD * 2 - 3 * 128) : 128;
            }

            if (kc == 0) {
                #pragma unroll
                for (int mi = 0; mi < 2; mi++)
                    #pragma unroll
                    for (int ni = 0; ni < 4; ni++)
                        #pragma unroll
                        for (int q = 0; q < 4; q++) acc[mi][ni][q] = 0.f;
            }

            uint32_t Bb = (kc & 1) ? Bbase1 : Bbase0;
            #pragma unroll
            for (int s = 0; s < 4; s++) {            // 4 k16 steps / 64-k chunk
                int ga = kc * 8 + s * 2 + aka;       // compile-time kc, s
                uint32_t a0[4], a1[4];
                ldsm_x4(a0, Arow0 + ((ga ^ sw) << 4));
                ldsm_x4(a1, Arow1 + ((ga ^ sw) << 4));
                int gb = s * 2 + bka;
                uint32_t b0[4], b1[4];
                ldsm_x4(b0, Bb + Brow0 + ((gb ^ sw) << 4));
                ldsm_x4(b1, Bb + Brow1 + ((gb ^ sw) << 4));
                mma_bf16(acc[0][0], a0, b0[0], b0[1]);
                mma_bf16(acc[0][1], a0, b0[2], b0[3]);
                mma_bf16(acc[1][0], a1, b0[0], b0[1]);
                mma_bf16(acc[1][1], a1, b0[2], b0[3]);
                mma_bf16(acc[0][2], a0, b1[0], b1[1]);
                mma_bf16(acc[0][3], a0, b1[2], b1[3]);
                mma_bf16(acc[1][2], a1, b1[0], b1[1]);
                mma_bf16(acc[1][3], a1, b1[2], b1[3]);
            }

            if (kc == 3) {
                int jb = cbase + jt * 128;
                if (jt == 0) {
                    // bootstrap: per-thread top-4 of its 8 cols per owned row
                    #pragma unroll
                    for (int mi = 0; mi < 2; mi++)
                        #pragma unroll
                        for (int qh = 0; qh < 2; qh++) {
                            int rl = wm * 32 + mi * 16 + qh * 8 + rq;
                            float bv[4] = {INF, INF, INF, INF};
                            int bc[4] = {0, 0, 0, 0};
                            #pragma unroll
                            for (int ni = 0; ni < 4; ni++)
                                #pragma unroll
                                for (int ql = 0; ql < 2; ql++) {
                                    int cl = wn * 32 + ni * 8 + cq2 + ql;
                                    float k = fmaf(-2.f, acc[mi][ni][qh * 2 + ql], sqs[cl]);
                                    if (k < bv[3]) {
                                        if (k < bv[2]) {
                                            bv[3] = bv[2]; bc[3] = bc[2];
                                            if (k < bv[1]) {
                                                bv[2] = bv[1]; bc[2] = bc[1];
                                                if (k < bv[0]) {
                                                    bv[1] = bv[0]; bc[1] = bc[0];
                                                    bv[0] = k; bc[0] = cl;
                                                } else { bv[1] = k; bc[1] = cl; }
                                            } else { bv[2] = k; bc[2] = cl; }
                                        } else { bv[3] = k; bc[3] = cl; }
                                    }
                                }
                            #pragma unroll
                            for (int s2 = 0; s2 < 4; s2++) {
                                int pos = atomicAdd(&cnt[rl], 1);
                                if (pos < CAP)
                                    buf[rl * CAP + pos] =
                                        ((unsigned long long)fkey_map(bv[s2]) << 32) |
                                        (unsigned)(jb + bc[s2]);
                            }
                        }
                } else {
                    // threshold filter: push survivors only
                    #pragma unroll
                    for (int mi = 0; mi < 2; mi++)
                        #pragma unroll
                        for (int qh = 0; qh < 2; qh++) {
                            float wv = wvreg[mi * 2 + qh];
                            int rl = wm * 32 + mi * 16 + qh * 8 + rq;
                            #pragma unroll
                            for (int ni = 0; ni < 4; ni++)
                                #pragma unroll
                                for (int ql = 0; ql < 2; ql++) {
                                    int cl = wn * 32 + ni * 8 + cq2 + ql;
                                    float k = fmaf(-2.f, acc[mi][ni][qh * 2 + ql], sqs[cl]);
                                    if (k < wv) {
                                        int pos = atomicAdd(&cnt[rl], 1);
                                        if (pos < CAP)
                                            buf[rl * CAP + pos] =
                                                ((unsigned long long)fkey_map(k) << 32) |
                                                (unsigned)(jb + cl);
                                    }
                                }
                        }
                }

                if ((jt & (jt + 1)) == 0) {   // window boundary: jt = 2^m - 1
                    __syncthreads();
                    if (t < 64) {
                        int n = cnt[t]; if (n > CAP) n = CAP;
                        unsigned long long* tk = &topk[t * TOPST];
                        for (int e = 0; e < n; e++) {
                            unsigned long long v = buf[t * CAP + e];
                            int pm = 0; unsigned long long mv = tk[0];
                            #pragma unroll
                            for (int k = 1; k < TOPK; k++)
                                if (tk[k] > mv) { mv = tk[k]; pm = k; }
                            if (v < mv) tk[pm] = v;
                        }
                        cnt[t] = 0;
                        unsigned long long mv = tk[0];
                        #pragma unroll
                        for (int k = 1; k < TOPK; k++)
                            if (tk[k] > mv) mv = tk[k];
                        wvv[t] = fkey_unmap((uint32_t)(mv >> 32));
                    }
                    __syncthreads();
                    #pragma unroll
                    for (int mi = 0; mi < 2; mi++)
                        #pragma unroll
                        for (int qh = 0; qh < 2; qh++)
                            wvreg[mi * 2 + qh] = wvv[wm * 32 + mi * 16 + qh * 8 + rq];
                }
            }
        }
    }

    // emit 16 candidates per (row, half); jt=31 consolidation already ran
    if (t < 64) {
        int row = rb + t;
        #pragma unroll
        for (int s = 0; s < TOPK; s++)
            g_pi[row * 32 + half * 16 + s] =
                (int)(topk[t * TOPST + s] & 0xffffffffULL);
    }
}

// ---------------- exact refine: warp-cooperative, coalesced -----------------
__global__ __launch_bounds__(256) void refine_kernel() {
    int t = threadIdx.x, w = t >> 5, l = t & 31;
    int i = blockIdx.x * 8 + w;
    const float4* fi4 = (const float4*)&g_f[i * DD];
    float4 a0 = fi4[l], a1 = fi4[l + 32];
    int jl = g_pi[i * 32 + l];
    float sql = g_sq[jl];
    unsigned long long pk = ~0ULL;
    #pragma unroll 8
    for (int c = 0; c < 32; c++) {
        int j = __shfl_sync(0xffffffffu, jl, c);
        float sq = __shfl_sync(0xffffffffu, sql, c);
        const float4* fj4 = (const float4*)&g_f[j * DD];
        float4 b0 = fj4[l], b1 = fj4[l + 32];
        float p = a0.x * b0.x;
        p = fmaf(a0.y, b0.y, p);
        p = fmaf(a0.z, b0.z, p);
        p = fmaf(a0.w, b0.w, p);
        p = fmaf(a1.x, b1.x, p);
        p = fmaf(a1.y, b1.y, p);
        p = fmaf(a1.z, b1.z, p);
        p = fmaf(a1.w, b1.w, p);
        #pragma unroll
        for (int o = 16; o > 0; o >>= 1)
            p += __shfl_xor_sync(0xffffffffu, p, o);
        float key = sq - 2.f * p;
        unsigned long long v =
            ((unsigned long long)fkey_map(key) << 32) | (unsigned)j;
        if (l == c) pk = v;
    }
    #pragma unroll
    for (int r = 0; r < KNN; r++) {
        unsigned long long m = pk;
        #pragma unroll
        for (int o = 16; o > 0; o >>= 1) {
            unsigned long long other = __shfl_xor_sync(0xffffffffu, m, o);
            if (other < m) m = other;
        }
        if (l == 0) g_idx[i * KNN + r] = (int)(m & 0xffffffffULL);
        if (pk == m) pk = 0xFFFFFFFFFFFFFFFFULL;
    }
}

// ---------------- Laplacian apply -------------------------------------------
__global__ __launch_bounds__(256) void zero_kernel() {
    int tid = blockIdx.x * blockDim.x + threadIdx.x;
    int stride = gridDim.x * blockDim.x;
    float4 z4 = make_float4(0.f, 0.f, 0.f, 0.f);
    for (int i = tid; i < NP * DD / 4; i += stride) ((float4*)g_z)[i] = z4;
    if (tid < NP) { g_bcnt[tid] = 0.f; g_sq[tid] = 0.f; }
}

__global__ __launch_bounds__(256) void scatter_kernel(const float* __restrict__ x) {
    __shared__ int sidx[4][KNN];
    int t = threadIdx.x;
    int i0 = blockIdx.x * 4;
    if (t < 4 * KNN) {
        int r = t / KNN, k = t % KNN;
        int e = g_idx[(i0 + r) * KNN + k];
        sidx[r][k] = e;
        atomicAdd(&g_bcnt[e], 1.0f);
    }
    __syncthreads();
    int s = t >> 6;
    int cq = (t & 63) << 2;
    const float cnorm = 0.31622776601683794f;  // 1/sqrt(10+1e-10)
    float4 xv = *(const float4*)&x[(i0 + s) * DD + cq];
    float4 y = make_float4(xv.x * cnorm, xv.y * cnorm, xv.z * cnorm, xv.w * cnorm);
    #pragma unroll
    for (int k = 0; k < KNN; k++) {
        int e = sidx[s][k];
        float* p = &g_z[e * DD + cq];
        asm volatile("red.global.add.v4.f32 [%0], {%1, %2, %3, %4};"
                     :: "l"(p), "f"(y.x), "f"(y.y), "f"(y.z), "f"(y.w) : "memory");
    }
}

__global__ __launch_bounds__(256) void gather_kernel(const float* __restrict__ x) {
    __shared__ int   sidx[4][KNN];
    __shared__ float sbis[4][KNN];
    int t = threadIdx.x;
    int i0 = blockIdx.x * 4;
    if (t < 4 * KNN) {
        int r = t / KNN, k = t % KNN;
        int e = g_idx[(i0 + r) * KNN + k];
        sidx[r][k] = e;
        sbis[r][k] = 1.0f / sqrtf(g_bcnt[e] + 1e-10f);
    }
    __syncthreads();
    int s = t >> 6;
    int cq = (t & 63) << 2;
    float4 acc = make_float4(0.f, 0.f, 0.f, 0.f);
    #pragma unroll
    for (int k = 0; k < KNN; k++) {
        int e = sidx[s][k];
        float b = sbis[s][k];
        float4 zv = *(const float4*)&g_z[e * DD + cq];
        acc.x = fmaf(b, zv.x, acc.x);
        acc.y = fmaf(b, zv.y, acc.y);
        acc.z = fmaf(b, zv.z, acc.z);
        acc.w = fmaf(b, zv.w, acc.w);
    }
    const float hc = 0.5f * 0.31622776601683794f;
    float4 xv = *(const float4*)&x[(i0 + s) * DD + cq];
    float4 h;
    h.x = xv.x - hc * acc.x;
    h.y = xv.y - hc * acc.y;
    h.z = xv.z - hc * acc.z;
    h.w = xv.w - hc * acc.w;
    *(float4*)&g_h[(i0 + s) * DD + cq] = h;
}

// ---------------- launch -----------------------------------------------------
extern "C" void kernel_launch(void* const* d_in, const int* in_sizes, int n_in,
                              void* d_out, int out_size) {
    const float* x    = (const float*)d_in[0];   // (8192, 256)
    const float* w    = (const float*)d_in[1];   // (256, 256)
    const float* wd   = (const float*)d_in[2];   // (256, 256)
    const float* bias = (const float*)d_in[3];   // (256,)
    float* out = (float*)d_out;                  // (8192, 256)

    const int KNN_SMEM = 108544;
    cudaFuncSetAttribute(knn_coarse_kernel,
                         cudaFuncAttributeMaxDynamicSharedMemorySize, KNN_SMEM);

    zero_kernel<<<1024, 256>>>();                       // g_z, g_bcnt, g_sq = 0
    gemm_f_kernel<<<dim3(DD / 64, NP / 64), 256>>>(x, wd);  // f, fb, sq (fused)
    knn_coarse_kernel<<<dim3(2, NP / 64), 256, KNN_SMEM>>>();
    refine_kernel<<<NP / 8, 256>>>();
    scatter_kernel<<<NP / 4, 256>>>(x);
    gather_kernel<<<NP / 4, 256>>>(x);
    gemm_out_kernel<<<dim3(DD / 64, NP / 64), 256>>>(w, bias, out);
}